// round 5
// baseline (speedup 1.0000x reference)
#include <cuda_runtime.h>

#define ALPHA 0.5f
#define BATA  0.01f
#define LAMDA 0.01f
#define GAMA  0.01f
#define DIM   64
#define BMAX  8192
#define MAXITEMS 64

__device__ int g_starts[BMAX + 1];

__device__ __forceinline__ void cp_async16(void* smem_dst, const void* gsrc) {
    unsigned saddr = (unsigned)__cvta_generic_to_shared(smem_dst);
    asm volatile("cp.async.cg.shared.global [%0], [%1], 16;" :: "r"(saddr), "l"(gsrc));
}

// starts[b] = first index i with segids[i] >= b; also zeroes out[0].
__global__ void bounds_kernel(const int* __restrict__ segids, int total, int B,
                              int* __restrict__ starts, float* __restrict__ out) {
    int i = blockIdx.x * blockDim.x + threadIdx.x;
    if (i == 0) out[0] = 0.0f;
    if (i < total) {
        int cur  = segids[i];
        int prev = (i == 0) ? -1 : segids[i - 1];
        for (int s = prev + 1; s <= cur; ++s) starts[s] = i;
        if (i == total - 1)
            for (int s = cur + 1; s <= B; ++s) starts[s] = total;
    }
    cudaTriggerProgrammaticLaunchCompletion();
}

__global__ __launch_bounds__(256)
void fism_kernel(const float* __restrict__ bu,
                 const float* __restrict__ bi,
                 const float* __restrict__ qi,
                 const float* __restrict__ pu,
                 const float* __restrict__ uin,
                 const int*   __restrict__ users,
                 const int*   __restrict__ pos_items,
                 const int*   __restrict__ neg_items,
                 int n_neg,
                 const int*   __restrict__ hist_items,
                 float* __restrict__ out)
{
    __shared__ float4 s_qi[MAXITEMS * 16];     // prefetched qi rows (cp.async)
    __shared__ float  s_bi[MAXITEMS];
    __shared__ float4 s_part[16][16];
    __shared__ float  s_ue[DIM];
    __shared__ float  s_loss, s_tp, s_bu;

    const int b   = blockIdx.x;
    const int tid = threadIdx.x;
    const int n_items = n_neg + 1;             // 51, <= MAXITEMS

    const float4* __restrict__ qi4 = (const float4*)qi;
    const float4* __restrict__ pu4 = (const float4*)pu;

    // ---- Pre-PDL: everything independent of bounds_kernel ----
    if (tid == 0) s_loss = 0.0f;
    if (tid == 32) {
        s_tp = rsqrtf(uin[b]);                 // uin^(-0.5)
        s_bu = bu[users[b]];
    }
    if (tid < n_items) {
        int row = (tid == 0) ? pos_items[b] : neg_items[b * n_neg + tid - 1];
        s_bi[tid] = bi[row];
    }

    // Prefetch all qi rows for this user into SMEM (overlaps PDL wait + phase A).
    {
        int rowreg[4];
        bool ok[4];
        #pragma unroll
        for (int k = 0; k < 4; k++) {
            int e = tid + (k << 8);            // element of n_items*16 float4s
            int j = e >> 4;
            ok[k] = (j < n_items);
            rowreg[k] = 0;
            if (ok[k])
                rowreg[k] = (j == 0) ? __ldg(&pos_items[b])
                                     : __ldg(&neg_items[b * n_neg + j - 1]);
        }
        #pragma unroll
        for (int k = 0; k < 4; k++) {
            int e = tid + (k << 8);
            if (ok[k])
                cp_async16(&s_qi[e], &qi4[rowreg[k] * 16 + (e & 15)]);
        }
        asm volatile("cp.async.commit_group;");
    }

    cudaGridDependencySynchronize();           // g_starts / out-zeroing visible

    const int start = g_starts[b];
    const int end   = g_starts[b + 1];

    // ---- Phase A: segment-sum of pu rows; direct idx loads, 4-deep batch ----
    const int f4 = tid & 15;                   // float4 lane within 64-float row
    const int r  = tid >> 4;                   // row group 0..15

    float4 acc = make_float4(0.f, 0.f, 0.f, 0.f);
    for (int i = start + r; i < end; i += 64) {
        int i0 = i, i1 = i + 16, i2 = i + 32, i3 = i + 48;
        int d0 = __ldg(&hist_items[i0]);
        int d1 = (i1 < end) ? __ldg(&hist_items[i1]) : 0;
        int d2 = (i2 < end) ? __ldg(&hist_items[i2]) : 0;
        int d3 = (i3 < end) ? __ldg(&hist_items[i3]) : 0;
        float4 z  = make_float4(0.f, 0.f, 0.f, 0.f);
        float4 v0 = __ldg(&pu4[d0 * 16 + f4]);
        float4 v1 = (i1 < end) ? __ldg(&pu4[d1 * 16 + f4]) : z;
        float4 v2 = (i2 < end) ? __ldg(&pu4[d2 * 16 + f4]) : z;
        float4 v3 = (i3 < end) ? __ldg(&pu4[d3 * 16 + f4]) : z;
        acc.x += v0.x + v1.x + v2.x + v3.x;
        acc.y += v0.y + v1.y + v2.y + v3.y;
        acc.z += v0.z + v1.z + v2.z + v3.z;
        acc.w += v0.w + v1.w + v2.w + v3.w;
    }
    s_part[r][f4] = acc;
    __syncthreads();

    // Reduce 16 partials per float4 lane; also BATA*||ue||^2
    if (tid < 16) {
        float4 t = s_part[0][tid];
        #pragma unroll
        for (int rr = 1; rr < 16; rr++) {
            float4 p = s_part[rr][tid];
            t.x += p.x; t.y += p.y; t.z += p.z; t.w += p.w;
        }
        ((float4*)s_ue)[tid] = t;
        float sq = t.x * t.x + t.y * t.y + t.z * t.z + t.w * t.w;
        #pragma unroll
        for (int off = 8; off; off >>= 1)
            sq += __shfl_down_sync(0x0000ffffu, sq, off, 16);
        if (tid == 0) atomicAdd(&s_loss, BATA * sq);
    }
    asm volatile("cp.async.wait_group 0;");
    __syncthreads();                            // s_ue + all cp.async data visible

    // ---- Phase B: 51 items from SMEM, 4 per half-warp ----
    const float tp  = s_tp;
    const float b_u = s_bu;
    const int lane = tid & 31;
    const int w    = tid >> 5;
    const int half = lane >> 4;
    const int fl   = lane & 15;
    const int hw   = (w << 1) + half;           // half-warp id 0..15

    const float4 ue4 = ((const float4*)s_ue)[fl];

    float part[4];
    bool  valid[4];
    float possq = 0.0f;

    #pragma unroll
    for (int k = 0; k < 4; k++) {
        int j = hw + (k << 4);
        valid[k] = (j < n_items);
        part[k] = 0.0f;
        if (valid[k]) {
            float4 q = s_qi[j * 16 + fl];
            part[k] = ue4.x * q.x + ue4.y * q.y + ue4.z * q.z + ue4.w * q.w;
            if (j == 0) possq = q.x * q.x + q.y * q.y + q.z * q.z + q.w * q.w;
        }
    }
    #pragma unroll
    for (int off = 8; off; off >>= 1) {
        part[0] += __shfl_down_sync(0xffffffffu, part[0], off, 16);
        part[1] += __shfl_down_sync(0xffffffffu, part[1], off, 16);
        part[2] += __shfl_down_sync(0xffffffffu, part[2], off, 16);
        part[3] += __shfl_down_sync(0xffffffffu, part[3], off, 16);
        possq   += __shfl_down_sync(0xffffffffu, possq,   off, 16);
    }

    float wloss = 0.0f;
    if (fl == 0) {
        #pragma unroll
        for (int k = 0; k < 4; k++) {
            int j = hw + (k << 4);
            if (valid[k]) {
                float bir = s_bi[j];
                float x = tp * part[k] + bir + b_u;
                float s = 1.0f / (1.0f + __expf(-x));
                if (j == 0) {
                    float e = 1.0f - s;
                    wloss += e * e + BATA * possq + LAMDA * bir * bir;
                } else {
                    wloss += s * s;
                }
            }
        }
    }
    wloss += __shfl_down_sync(0xffffffffu, wloss, 16);
    if (lane == 0) atomicAdd(&s_loss, wloss);

    if (tid == 0) atomicAdd(&s_loss, LAMDA * GAMA * b_u * b_u);
    __syncthreads();

    if (tid == 0) atomicAdd(out, s_loss);
}

extern "C" void kernel_launch(void* const* d_in, const int* in_sizes, int n_in,
                              void* d_out, int out_size)
{
    const float* bu          = (const float*)d_in[0];
    const float* bi          = (const float*)d_in[1];
    const float* qi          = (const float*)d_in[2];
    const float* pu          = (const float*)d_in[3];
    const float* uin         = (const float*)d_in[4];
    const int*   users       = (const int*)  d_in[5];
    const int*   pos_items   = (const int*)  d_in[6];
    const int*   neg_items   = (const int*)  d_in[7];
    const int*   hist_items  = (const int*)  d_in[8];
    const int*   hist_segids = (const int*)  d_in[9];

    const int B     = in_sizes[5];
    const int total = in_sizes[8];
    const int n_neg = in_sizes[7] / B;

    float* out = (float*)d_out;

    int* starts;
    cudaGetSymbolAddress((void**)&starts, g_starts);

    bounds_kernel<<<(total + 255) / 256, 256>>>(hist_segids, total, B, starts, out);

    cudaLaunchConfig_t cfg = {};
    cfg.gridDim  = dim3(B);
    cfg.blockDim = dim3(256);
    cfg.stream   = 0;
    cudaLaunchAttribute attr[1];
    attr[0].id = cudaLaunchAttributeProgrammaticStreamSerialization;
    attr[0].val.programmaticStreamSerializationAllowed = 1;
    cfg.attrs    = attr;
    cfg.numAttrs = 1;
    cudaLaunchKernelEx(&cfg, fism_kernel, bu, bi, qi, pu, uin, users,
                       pos_items, neg_items, n_neg, hist_items, out);
}